// round 11
// baseline (speedup 1.0000x reference)
#include <cuda_runtime.h>

// ---------------------------------------------------------------------------
// CustomLSTM: B=2048, T=256, I=5, H=50, O=1
//
// R11: two gate rows per thread (halved LDS:FMA ratio, proven in R7/R8) at
// ONE block per SM with 400 threads so the ~140-reg working set fits without
// spilling (cap = 65536/416 = 157; the 2-blocks/SM cap of 128 forced spills).
//   grid=148: blocks 0..123 own NB=14 batches, 124..147 own NB=13.
//   Thread = (pair p in [0,100), quarter q in [0,4)): owns gate rows p and
//   p+100 -> (f_j, c~_j) for p<50 (j=p) or (i_j, o_j) for p>=50 (j=p-50),
//   covering batches b = q, q+4, q+8, q+12 (b < NB). Each h LDS.128 feeds
//   FMAs of BOTH rows. Both gate results stored as one STS.64 into
//   gbS[b][p]. Phase B: <=2 (batch,unit) tasks/thread, c-state in registers.
//   2 barriers/step, weights k-packed f32x2 in registers, x prefetched.
// ---------------------------------------------------------------------------

typedef unsigned long long ull;

constexpr int T     = 256;
constexpr int I     = 5;
constexpr int H     = 50;
constexpr int NTH   = 400;
constexpr int NPAIR = 100;
constexpr int GRID  = 148;
constexpr int BIGB  = 124;    // blocks [0,124) have NB=14, rest NB=13
constexpr int NBMAX = 14;
constexpr int HROW  = 52;     // 208B row stride
constexpr int XR    = 8;      // x row stride (floats) = 32B

__device__ __forceinline__ ull fma2(ull a, ull b, ull c) {
    ull d;
    asm("fma.rn.f32x2 %0, %1, %2, %3;" : "=l"(d) : "l"(a), "l"(b), "l"(c));
    return d;
}
__device__ __forceinline__ ull pack2(float x, float y) {
    ull r;
    asm("mov.b64 %0, {%1, %2};" : "=l"(r) : "f"(x), "f"(y));
    return r;
}
__device__ __forceinline__ float2 unpack2(ull v) {
    float2 r;
    asm("mov.b64 {%0, %1}, %2;" : "=f"(r.x), "=f"(r.y) : "l"(v));
    return r;
}
__device__ __forceinline__ float sigf(float x) {
    return __fdividef(1.0f, 1.0f + __expf(-x));
}
__device__ __forceinline__ float tanh_fast(float x) {
    float a = fabsf(x);
    float e = __expf(-2.0f * a);
    float t = __fdividef(1.0f - e, 1.0f + e);
    return copysignf(t, x);
}

__global__ void __launch_bounds__(NTH, 1) lstm_fused_kernel(
    const float* __restrict__ x,
    const float* __restrict__ Wxf, const float* __restrict__ bxf,
    const float* __restrict__ Wxi, const float* __restrict__ bxi,
    const float* __restrict__ Wxc, const float* __restrict__ bxc,
    const float* __restrict__ Wxo, const float* __restrict__ bxo,
    const float* __restrict__ Whf, const float* __restrict__ bhf,
    const float* __restrict__ Whi, const float* __restrict__ bhi,
    const float* __restrict__ Whc, const float* __restrict__ bhc,
    const float* __restrict__ Who, const float* __restrict__ bho,
    const float* __restrict__ bf,  const float* __restrict__ bi,
    const float* __restrict__ bc,  const float* __restrict__ bo,
    const float* __restrict__ Wfc, const float* __restrict__ bfc,
    float* __restrict__ out)
{
    // gbS[b][p] = float2( gate row p, gate row p+100 ) for batch b
    //   p <  50: (f_j, c~_j), j = p
    //   p >= 50: (i_j, o_j),  j = p - 50
    __shared__ __align__(16) float2 gbS[NBMAX][NPAIR];
    __shared__ __align__(16) float  hS[NBMAX][HROW];
    __shared__ __align__(16) float  xS[2][NBMAX][XR];

    const int tid = threadIdx.x;
    const int bid = blockIdx.x;
    const int b0  = (bid < BIGB) ? bid * 14 : BIGB * 14 + (bid - BIGB) * 13;
    const int NB  = (bid < BIGB) ? 14 : 13;

    const int pair = tid % NPAIR;    // 0..99
    const int qtr  = tid / NPAIR;    // 0..3
    const int j    = (pair < 50) ? pair : pair - 50;

    const float *whA, *wxA, *whB, *wxB;
    float btA, btB;
    if (pair < 50) {
        whA = Whf + j * H; wxA = Wxf + j * I; btA = bxf[j] + bhf[j] + bf[j];
        whB = Whc + j * H; wxB = Wxc + j * I; btB = bxc[j] + bhc[j] + bc[j];
    } else {
        whA = Whi + j * H; wxA = Wxi + j * I; btA = bxi[j] + bhi[j] + bi[j];
        whB = Who + j * H; wxB = Wxo + j * I; btB = bxo[j] + bho[j] + bo[j];
    }

    ull w2a[H / 2], w2b[H / 2];          // 100 regs (the payload)
#pragma unroll
    for (int k = 0; k < H / 2; k++) {
        w2a[k] = pack2(whA[2 * k], whA[2 * k + 1]);
        w2b[k] = pack2(whB[2 * k], whB[2 * k + 1]);
    }
    const float wxa0 = wxA[0], wxa1 = wxA[1], wxa2 = wxA[2], wxa3 = wxA[3], wxa4 = wxA[4];
    const float wxb0 = wxB[0], wxb1 = wxB[1], wxb2 = wxB[2], wxb3 = wxB[3], wxb4 = wxB[4];

    // ---- init shared
    for (int idx = tid; idx < NBMAX * HROW; idx += NTH) (&hS[0][0])[idx] = 0.0f;
    for (int idx = tid; idx < 2 * NBMAX * XR; idx += NTH) (&xS[0][0][0])[idx] = 0.0f;

    // ---- stage x(t=0)
    const int lb = tid / I, pi = tid - lb * I;   // prefetch coords (tid < NB*I)
    if (tid < NB * I)
        xS[0][lb][pi] = x[(size_t)(b0 + lb) * (T * I) + pi];

    // ---- phase-B fixed tasks: task0 = tid, task1 = tid + 400
    const int ub0 = tid / H,     uj0 = tid - ub0 * H;   // ub0 in 0..7
    const int ub1 = 8 + ub0;                            // 8..15
    const bool has1 = (tid + NTH) < NB * H;             // 300 or 250 threads
    const float2* gfc0 = &gbS[ub0][uj0];
    const float2* gfc1 = &gbS[ub1 < NBMAX ? ub1 : 0][uj0];
    float* hw0 = &hS[ub0][uj0];
    float* hw1 = &hS[ub1 < NBMAX ? ub1 : 0][uj0];
    float c0 = 0.0f, c1 = 0.0f;

    __syncthreads();

    // =============================== time loop ==============================
    for (int t = 0; t < T; t++) {
        // prefetch x(t+1) (independent LDG, hidden under phase A)
        float pf = 0.0f;
        const bool dof = (tid < NB * I) && (t + 1 < T);
        if (dof) pf = x[(size_t)(b0 + lb) * (T * I) + (t + 1) * I + pi];

        // ---- phase A: both gate rows for batches b = qtr, qtr+4, qtr+8, ...
        const float* xbase = &xS[t & 1][0][0];
#pragma unroll
        for (int bb = 0; bb < 4; bb++) {
            const int b = qtr + 4 * bb;
            if (b < NB) {
                const float* hp = &hS[b][0];
                ull ae0 = pack2(btA, 0.0f), ao0 = 0ull;
                ull ae1 = pack2(btB, 0.0f), ao1 = 0ull;
#pragma unroll
                for (int c = 0; c < 12; c++) {
                    ulonglong2 hv = *(const ulonglong2*)(hp + 4 * c);
                    ae0 = fma2(hv.x, w2a[2 * c],     ae0);
                    ao0 = fma2(hv.y, w2a[2 * c + 1], ao0);
                    ae1 = fma2(hv.x, w2b[2 * c],     ae1);
                    ao1 = fma2(hv.y, w2b[2 * c + 1], ao1);
                }
                {
                    ull h48 = *(const ull*)(hp + 48);
                    ae0 = fma2(h48, w2a[24], ae0);
                    ae1 = fma2(h48, w2b[24], ae1);
                }
                // scalar x projection
                const float* xp = xbase + b * XR;
                float4 xv = *(const float4*)xp;
                float  x4 = xp[4];
                float xdA = wxa0 * xv.x + wxa1 * xv.y;
                float xdB = wxb0 * xv.x + wxb1 * xv.y;
                xdA += wxa2 * xv.z + wxa3 * xv.w + wxa4 * x4;
                xdB += wxb2 * xv.z + wxb3 * xv.w + wxb4 * x4;

                float2 e0 = unpack2(ae0), o0 = unpack2(ao0);
                float2 e1 = unpack2(ae1), o1 = unpack2(ao1);
                gbS[b][pair] = make_float2((e0.x + o0.x) + (e0.y + o0.y) + xdA,
                                           (e1.x + o1.x) + (e1.y + o1.y) + xdB);
            }
        }
        __syncthreads();

        if (dof) xS[(t + 1) & 1][lb][pi] = pf;

        // ---- phase B: up to 2 (batch,unit) tasks per thread
        {
            float2 fc0 = gfc0[0];
            float2 io0 = gfc0[50];
            c0 = sigf(fc0.x) * c0 + sigf(io0.x) * tanh_fast(fc0.y);
            *hw0 = sigf(io0.y) * tanh_fast(c0);
            if (has1) {
                float2 fc1 = gfc1[0];
                float2 io1 = gfc1[50];
                c1 = sigf(fc1.x) * c1 + sigf(io1.x) * tanh_fast(fc1.y);
                *hw1 = sigf(io1.y) * tanh_fast(c1);
            }
        }
        __syncthreads();
    }

    // ---- final projection: out[b] = h_T[b] . Wfc + bfc   (O = 1)
    if (tid < NB) {
        const float* hp = &hS[tid][0];
        float s = bfc[0];
#pragma unroll
        for (int k = 0; k < H; k++) s += hp[k] * Wfc[k];
        out[b0 + tid] = s;
    }
}

extern "C" void kernel_launch(void* const* d_in, const int* in_sizes, int n_in,
                              void* d_out, int out_size)
{
    (void)in_sizes; (void)n_in; (void)out_size;
    const float* x   = (const float*)d_in[0];
    const float* Wxf = (const float*)d_in[1];
    const float* bxf = (const float*)d_in[2];
    const float* Wxi = (const float*)d_in[3];
    const float* bxi = (const float*)d_in[4];
    const float* Wxc = (const float*)d_in[5];
    const float* bxc = (const float*)d_in[6];
    const float* Wxo = (const float*)d_in[7];
    const float* bxo = (const float*)d_in[8];
    const float* Whf = (const float*)d_in[9];
    const float* bhf = (const float*)d_in[10];
    const float* Whi = (const float*)d_in[11];
    const float* bhi = (const float*)d_in[12];
    const float* Whc = (const float*)d_in[13];
    const float* bhc = (const float*)d_in[14];
    const float* Who = (const float*)d_in[15];
    const float* bho = (const float*)d_in[16];
    const float* bf  = (const float*)d_in[17];
    const float* bi  = (const float*)d_in[18];
    const float* bc  = (const float*)d_in[19];
    const float* bo  = (const float*)d_in[20];
    const float* Wfc = (const float*)d_in[21];
    const float* bfc = (const float*)d_in[22];
    float* out = (float*)d_out;

    lstm_fused_kernel<<<GRID, NTH>>>(
        x,
        Wxf, bxf, Wxi, bxi, Wxc, bxc, Wxo, bxo,
        Whf, bhf, Whi, bhi, Whc, bhc, Who, bho,
        bf, bi, bc, bo,
        Wfc, bfc,
        out);
}

// round 12
// speedup vs baseline: 1.3621x; 1.3621x over previous
#include <cuda_runtime.h>

// ---------------------------------------------------------------------------
// CustomLSTM: B=2048, T=256, I=5, H=50, O=1
//
// R12 = R6 (best: 494us) with ONE change: activations use the hardware
// tanh.approx.f32 instruction (sm_75+): tanh = 1 MUFU; sigmoid(x) =
// 0.5*tanh(0.5x)+0.5 = 1 MUFU + FMA. Replaces __expf+__fdividef chains
// (2 MUFU + div each) -> phase-B MUFU count halves and the per-task serial
// chain shortens ~2x. Everything else identical to R6:
//   grid=296 (2 independent blocks/SM), 200 threads, NB=7/6, weights
//   k-packed f32x2 in registers (1 gate row/thread), 2 barriers/step,
//   c-state in registers, x prefetched one step ahead.
// ---------------------------------------------------------------------------

typedef unsigned long long ull;

constexpr int T    = 256;
constexpr int I    = 5;
constexpr int H    = 50;
constexpr int NTH  = 200;
constexpr int GRID = 296;
constexpr int BIGB = 272;    // blocks [0,272) have NB=7, rest NB=6
constexpr int NBMAX = 7;
constexpr int HROW = 52;     // 208B row stride, 16B multiple
constexpr int XR   = 8;      // x row stride (floats) = 32B

__device__ __forceinline__ ull fma2(ull a, ull b, ull c) {
    ull d;
    asm("fma.rn.f32x2 %0, %1, %2, %3;" : "=l"(d) : "l"(a), "l"(b), "l"(c));
    return d;
}
__device__ __forceinline__ ull pack2(float x, float y) {
    ull r;
    asm("mov.b64 %0, {%1, %2};" : "=l"(r) : "f"(x), "f"(y));
    return r;
}
__device__ __forceinline__ float2 unpack2(ull v) {
    float2 r;
    asm("mov.b64 {%0, %1}, %2;" : "=f"(r.x), "=f"(r.y) : "l"(v));
    return r;
}
__device__ __forceinline__ float tanha(float x) {
    float r;
    asm("tanh.approx.f32 %0, %1;" : "=f"(r) : "f"(x));
    return r;
}
__device__ __forceinline__ float sigf(float x) {
    return fmaf(0.5f, tanha(0.5f * x), 0.5f);
}

__global__ void __launch_bounds__(NTH, 2) lstm_fused_kernel(
    const float* __restrict__ x,
    const float* __restrict__ Wxf, const float* __restrict__ bxf,
    const float* __restrict__ Wxi, const float* __restrict__ bxi,
    const float* __restrict__ Wxc, const float* __restrict__ bxc,
    const float* __restrict__ Wxo, const float* __restrict__ bxo,
    const float* __restrict__ Whf, const float* __restrict__ bhf,
    const float* __restrict__ Whi, const float* __restrict__ bhi,
    const float* __restrict__ Whc, const float* __restrict__ bhc,
    const float* __restrict__ Who, const float* __restrict__ bho,
    const float* __restrict__ bf,  const float* __restrict__ bi,
    const float* __restrict__ bc,  const float* __restrict__ bo,
    const float* __restrict__ Wfc, const float* __restrict__ bfc,
    float* __restrict__ out)
{
    __shared__ __align__(16) float gbS[NBMAX][4 * H];   // gate pre-activations
    __shared__ __align__(16) float hS[NBMAX][HROW];     // h state
    __shared__ __align__(16) float xS[2][NBMAX][XR];    // x double buffer

    const int tid = threadIdx.x;
    const int bid = blockIdx.x;
    const int b0  = (bid < BIGB) ? bid * 7 : BIGB * 7 + (bid - BIGB) * 6;
    const int NB  = (bid < BIGB) ? 7 : 6;

    const int g = tid;          // gate row 0..199
    const int q = g / H;        // 0=f 1=i 2=c 3=o
    const int j = g - q * H;

    // ---- weights for this gate row -> registers (k-packed f32x2)
    const float* whp;
    const float* wxp;
    float bt;
    if (q == 0)      { whp = Whf + j * H; wxp = Wxf + j * I; bt = bxf[j] + bhf[j] + bf[j]; }
    else if (q == 1) { whp = Whi + j * H; wxp = Wxi + j * I; bt = bxi[j] + bhi[j] + bi[j]; }
    else if (q == 2) { whp = Whc + j * H; wxp = Wxc + j * I; bt = bxc[j] + bhc[j] + bc[j]; }
    else             { whp = Who + j * H; wxp = Wxo + j * I; bt = bxo[j] + bho[j] + bo[j]; }

    ull w2[H / 2];
#pragma unroll
    for (int k = 0; k < H / 2; k++) w2[k] = pack2(whp[2 * k], whp[2 * k + 1]);
    const ull wx01 = pack2(wxp[0], wxp[1]);
    const ull wx23 = pack2(wxp[2], wxp[3]);
    const ull wx4c = pack2(wxp[4], 0.0f);

    // ---- init shared
    for (int idx = tid; idx < NBMAX * HROW; idx += NTH) (&hS[0][0])[idx] = 0.0f;
    for (int idx = tid; idx < 2 * NBMAX * XR; idx += NTH) (&xS[0][0][0])[idx] = 0.0f;

    // ---- stage x(t=0)
    const int lb = tid / I, pi = tid - lb * I;   // prefetch coords (tid < NB*I)
    if (tid < NB * I)
        xS[0][lb][pi] = x[(size_t)(b0 + lb) * (T * I) + pi];

    // ---- phase-B task coords: task0 = tid, task1 = tid + 200
    const int ub0 = tid / H,      uj0 = tid - ub0 * H;        // ub0 in 0..3
    const int ub1 = 4 + tid / H,  uj1 = uj0;                  // ub1 in 4..7
    const bool has1 = tid < (NB - 4) * H;                     // 150 or 100
    float c0 = 0.0f, c1 = 0.0f;

    __syncthreads();

#define A_ONE(b_) do {                                                       \
        const float* hp_ = &hS[b_][0];                                       \
        ull ae_ = pack2(bt, 0.0f);                                           \
        ull ao_ = 0ull;                                                      \
        _Pragma("unroll")                                                    \
        for (int c_ = 0; c_ < 12; c_++) {                                    \
            ulonglong2 hv_ = *(const ulonglong2*)(hp_ + 4 * c_);             \
            ae_ = fma2(hv_.x, w2[2 * c_],     ae_);                          \
            ao_ = fma2(hv_.y, w2[2 * c_ + 1], ao_);                          \
        }                                                                    \
        ull h48_ = *(const ull*)(hp_ + 48);                                  \
        ae_ = fma2(h48_, w2[24], ae_);                                       \
        const float* xp_ = &xS[t & 1][b_][0];                                \
        ulonglong2 xv_ = *(const ulonglong2*)xp_;                            \
        ae_ = fma2(xv_.x, wx01, ae_);                                        \
        ao_ = fma2(xv_.y, wx23, ao_);                                        \
        ull x4_ = *(const ull*)(xp_ + 4);                                    \
        ae_ = fma2(x4_, wx4c, ae_);                                          \
        float2 e_ = unpack2(ae_), o_ = unpack2(ao_);                         \
        gbS[b_][g] = (e_.x + o_.x) + (e_.y + o_.y);                          \
    } while (0)

    // =============================== time loop ==============================
    for (int t = 0; t < T; t++) {
        // prefetch x(t+1) (independent LDG, hidden under phase A)
        float pf = 0.0f;
        const bool dof = (tid < NB * I) && (t + 1 < T);
        if (dof) pf = x[(size_t)(b0 + lb) * (T * I) + (t + 1) * I + pi];

        // ---- phase A: gate g for all NB batches
        A_ONE(0); A_ONE(1); A_ONE(2);
        A_ONE(3); A_ONE(4); A_ONE(5);
        if (NB > 6) A_ONE(6);
        __syncthreads();

        if (dof) xS[(t + 1) & 1][lb][pi] = pf;

        // ---- phase B: up to 2 (batch,unit) tasks per thread (tanh.approx)
        {
            float gf0 = gbS[ub0][uj0];
            float gi0 = gbS[ub0][H + uj0];
            float gc0 = gbS[ub0][2 * H + uj0];
            float go0 = gbS[ub0][3 * H + uj0];
            float gf1 = 0.f, gi1 = 0.f, gc1 = 0.f, go1 = 0.f;
            if (has1) {
                gf1 = gbS[ub1][uj1];
                gi1 = gbS[ub1][H + uj1];
                gc1 = gbS[ub1][2 * H + uj1];
                go1 = gbS[ub1][3 * H + uj1];
            }
            c0 = sigf(gf0) * c0 + sigf(gi0) * tanha(gc0);
            hS[ub0][uj0] = sigf(go0) * tanha(c0);
            if (has1) {
                c1 = sigf(gf1) * c1 + sigf(gi1) * tanha(gc1);
                hS[ub1][uj1] = sigf(go1) * tanha(c1);
            }
        }
        __syncthreads();
    }
#undef A_ONE

    // ---- final projection: out[b] = h_T[b] . Wfc + bfc   (O = 1)
    if (tid < NB) {
        const float* hp = &hS[tid][0];
        float s = bfc[0];
#pragma unroll
        for (int k = 0; k < H; k++) s += hp[k] * Wfc[k];
        out[b0 + tid] = s;
    }
}

extern "C" void kernel_launch(void* const* d_in, const int* in_sizes, int n_in,
                              void* d_out, int out_size)
{
    (void)in_sizes; (void)n_in; (void)out_size;
    const float* x   = (const float*)d_in[0];
    const float* Wxf = (const float*)d_in[1];
    const float* bxf = (const float*)d_in[2];
    const float* Wxi = (const float*)d_in[3];
    const float* bxi = (const float*)d_in[4];
    const float* Wxc = (const float*)d_in[5];
    const float* bxc = (const float*)d_in[6];
    const float* Wxo = (const float*)d_in[7];
    const float* bxo = (const float*)d_in[8];
    const float* Whf = (const float*)d_in[9];
    const float* bhf = (const float*)d_in[10];
    const float* Whi = (const float*)d_in[11];
    const float* bhi = (const float*)d_in[12];
    const float* Whc = (const float*)d_in[13];
    const float* bhc = (const float*)d_in[14];
    const float* Who = (const float*)d_in[15];
    const float* bho = (const float*)d_in[16];
    const float* bf  = (const float*)d_in[17];
    const float* bi  = (const float*)d_in[18];
    const float* bc  = (const float*)d_in[19];
    const float* bo  = (const float*)d_in[20];
    const float* Wfc = (const float*)d_in[21];
    const float* bfc = (const float*)d_in[22];
    float* out = (float*)d_out;

    lstm_fused_kernel<<<GRID, NTH>>>(
        x,
        Wxf, bxf, Wxi, bxi, Wxc, bxc, Wxo, bxo,
        Whf, bhf, Whi, bhi, Whc, bhc, Who, bho,
        bf, bi, bc, bo,
        Wfc, bfc,
        out);
}